// round 2
// baseline (speedup 1.0000x reference)
#include <cuda_runtime.h>

// ---------------------------------------------------------------------------
// SoluModel fused pipeline, fp32 baseline.
// B=16, L=1024, D=640, D2=1280. All activations [B, C, LPAD] with interior
// at column OFF..OFF+L-1; columns OFF-1 and OFF+L are zero (conv SAME pad).
// ---------------------------------------------------------------------------

#define BN   16
#define LL   1024
#define DD   640
#define DD2  1280
#define LPAD 1032   // padded row length (keeps float4 alignment with OFF=4)
#define OFF  4

// ------------------------- device scratch buffers --------------------------
__device__ float g_featsT[(size_t)BN * DD  * LPAD];  // feats transposed [B,D,LPAD]
__device__ float g_act1  [(size_t)BN * DD2 * LPAD];  // conv stage buffer
__device__ float g_act2  [(size_t)BN * DD2 * LPAD];  // conv stage buffer
__device__ float g_cv3   [(size_t)BN * DD  * LPAD];  // cv conv3 out
__device__ float g_Wmat  [(size_t)BN * LL  * LL];    // pooling weight matrix
__device__ float g_cat   [(size_t)BN * LL  * (2*DD)];// [out_sa | out_conv]
__device__ float g_arow  [BN * LL];                  // 1/(1e-5 + 2*std^2)
__device__ float g_wsm   [BN * LL];                  // softmax(w channel)
__device__ float2 g_part [BN * 80];                  // LN partial (sum, sumsq)

// ------------------------------ init pads ----------------------------------
__global__ void init_pads_kernel() {
    int idx = blockIdx.x * blockDim.x + threadIdx.x;
    const int nfT = BN * DD, na = BN * DD2;
    float* base; int r;
    if      (idx < nfT)            { base = g_featsT; r = idx; }
    else if (idx < nfT + na)       { base = g_act1;   r = idx - nfT; }
    else if (idx < nfT + 2*na)     { base = g_act2;   r = idx - nfT - na; }
    else if (idx < nfT + 2*na + BN*DD) { base = g_cv3; r = idx - nfT - 2*na; }
    else return;
    base[(size_t)r * LPAD + (OFF - 1)]  = 0.f;
    base[(size_t)r * LPAD + (OFF + LL)] = 0.f;
}

// --------------------------- transpose feats -------------------------------
// feats [B,L,D] -> g_featsT [B,D,LPAD] interior
__global__ void transpose_feats_kernel(const float* __restrict__ feats) {
    __shared__ float t[32][33];
    int b = blockIdx.z;
    int d0 = blockIdx.x * 32, l0 = blockIdx.y * 32;
    int tx = threadIdx.x, ty = threadIdx.y;
#pragma unroll
    for (int y = 0; y < 32; y += 8)
        t[ty + y][tx] = feats[((size_t)b * LL + l0 + ty + y) * DD + d0 + tx]; // t[l][d]
    __syncthreads();
#pragma unroll
    for (int y = 0; y < 32; y += 8)
        g_featsT[((size_t)b * DD + d0 + ty + y) * LPAD + OFF + l0 + tx] = t[tx][ty + y];
}

// ------------------------------ conv GEMM ----------------------------------
// y[b,o,l] = sum_{i,t} w[o,i,t] * xpad[b,i,l+t-1] + bias[o]
// As NT GEMM: A = w [M, K=3*IC] (K-contiguous), B[n=l, k] = xpad[b, k/3, l + k%3]
// Writes per-block LN partials (deterministic, no atomics).
__global__ __launch_bounds__(256) void conv_gemm_kernel(
    const float* __restrict__ Aw, const float* __restrict__ bias,
    const float* __restrict__ Xpad, float* __restrict__ Ypad,
    int M, int IC)
{
    const int K  = 3 * IC;
    const int b  = blockIdx.z;
    const int m0 = blockIdx.y * 128, n0 = blockIdx.x * 128;
    const int tid = threadIdx.x;
    __shared__ float As[16][128];
    __shared__ float Bs[16][128];
    float acc[8][8];
#pragma unroll
    for (int i = 0; i < 8; ++i)
#pragma unroll
        for (int j = 0; j < 8; ++j) acc[i][j] = 0.f;

    const int mS = (tid >> 4) * 8, nS = (tid & 15) * 8;
    const int ar = tid >> 2, ac = (tid & 3) * 4;
    const int bn = tid & 127, bk = tid >> 7;
    const float* Xb = Xpad + (size_t)b * IC * LPAD + n0 + (OFF - 1);

    for (int k0 = 0; k0 < K; k0 += 16) {
#pragma unroll
        for (int h = 0; h < 2; ++h) {
            int row = ar + h * 64;
            float4 v = *(const float4*)(Aw + (size_t)(m0 + row) * K + k0 + ac);
            As[ac + 0][row] = v.x; As[ac + 1][row] = v.y;
            As[ac + 2][row] = v.z; As[ac + 3][row] = v.w;
        }
#pragma unroll
        for (int h = 0; h < 8; ++h) {
            int k  = bk + h * 2;
            int kk = k0 + k;
            int ic = kk / 3;
            int t  = kk - ic * 3;
            Bs[k][bn] = Xb[(size_t)ic * LPAD + bn + t];
        }
        __syncthreads();
#pragma unroll
        for (int kk = 0; kk < 16; ++kk) {
            float rm[8], rn[8];
            *(float4*)&rm[0] = *(const float4*)&As[kk][mS];
            *(float4*)&rm[4] = *(const float4*)&As[kk][mS + 4];
            *(float4*)&rn[0] = *(const float4*)&Bs[kk][nS];
            *(float4*)&rn[4] = *(const float4*)&Bs[kk][nS + 4];
#pragma unroll
            for (int i = 0; i < 8; ++i)
#pragma unroll
                for (int j = 0; j < 8; ++j)
                    acc[i][j] = fmaf(rm[i], rn[j], acc[i][j]);
        }
        __syncthreads();
    }

    float s = 0.f, q = 0.f;
#pragma unroll
    for (int i = 0; i < 8; ++i) {
        int m = m0 + mS + i;
        float bv = bias[m];
        float* yr = Ypad + ((size_t)b * M + m) * LPAD + OFF + n0 + nS;
        float v0[8];
#pragma unroll
        for (int j = 0; j < 8; ++j) { float v = acc[i][j] + bv; v0[j] = v; s += v; q += v * v; }
        *(float4*)yr       = make_float4(v0[0], v0[1], v0[2], v0[3]);
        *(float4*)(yr + 4) = make_float4(v0[4], v0[5], v0[6], v0[7]);
    }
#pragma unroll
    for (int o = 16; o > 0; o >>= 1) {
        s += __shfl_xor_sync(0xffffffffu, s, o);
        q += __shfl_xor_sync(0xffffffffu, q, o);
    }
    __shared__ float2 rb[8];
    if ((tid & 31) == 0) rb[tid >> 5] = make_float2(s, q);
    __syncthreads();
    if (tid == 0) {
        float S = 0.f, Q = 0.f;
#pragma unroll
        for (int i = 0; i < 8; ++i) { S += rb[i].x; Q += rb[i].y; }
        g_part[(size_t)b * 80 + blockIdx.y * gridDim.x + blockIdx.x] = make_float2(S, Q);
    }
}

// --------------------------- LayerNorm + Leaky ------------------------------
__global__ __launch_bounds__(256) void ln_leaky_kernel(
    float* __restrict__ X, int C, int nPart)
{
    int b = blockIdx.y, tid = threadIdx.x;
    float s = 0.f, q = 0.f;
    if (tid < nPart) { float2 p = g_part[(size_t)b * 80 + tid]; s = p.x; q = p.y; }
#pragma unroll
    for (int o = 16; o > 0; o >>= 1) {
        s += __shfl_xor_sync(0xffffffffu, s, o);
        q += __shfl_xor_sync(0xffffffffu, q, o);
    }
    __shared__ float2 rb[8];
    __shared__ float sm[2];
    if ((tid & 31) == 0) rb[tid >> 5] = make_float2(s, q);
    __syncthreads();
    if (tid == 0) {
        float S = 0.f, Q = 0.f;
        for (int i = 0; i < 8; ++i) { S += rb[i].x; Q += rb[i].y; }
        float inv  = 1.f / ((float)C * (float)LL);
        float mean = S * inv;
        float var  = Q * inv - mean * mean;
        sm[0] = mean; sm[1] = rsqrtf(var + 1e-5f);
    }
    __syncthreads();
    float mean = sm[0], rstd = sm[1];
    size_t total = (size_t)C * LL;
    for (size_t idx = (size_t)blockIdx.x * 256 + tid; idx < total; idx += (size_t)gridDim.x * 256) {
        size_t c = idx >> 10;
        int l = (int)(idx & 1023);
        float* p = X + ((size_t)b * C + c) * LPAD + OFF + l;
        float v = (*p - mean) * rstd;
        *p = v >= 0.f ? v : 0.01f * v;
    }
}

// ------------------------ reductions (1024-thread block) --------------------
__device__ __forceinline__ float warpSum(float v) {
#pragma unroll
    for (int o = 16; o > 0; o >>= 1) v += __shfl_xor_sync(0xffffffffu, v, o);
    return v;
}
__device__ __forceinline__ float warpMax(float v) {
#pragma unroll
    for (int o = 16; o > 0; o >>= 1) v = fmaxf(v, __shfl_xor_sync(0xffffffffu, v, o));
    return v;
}
__device__ float blockSum(float v, float* rbuf) {
    int lane = threadIdx.x & 31, wid = threadIdx.x >> 5;
    v = warpSum(v);
    if (lane == 0) rbuf[wid] = v;
    __syncthreads();
    if (wid == 0) {
        float r = (lane < 32) ? rbuf[lane] : 0.f;
        r = warpSum(r);
        if (lane == 0) rbuf[32] = r;
    }
    __syncthreads();
    float r = rbuf[32];
    __syncthreads();
    return r;
}
__device__ float blockMax(float v, float* rbuf) {
    int lane = threadIdx.x & 31, wid = threadIdx.x >> 5;
    v = warpMax(v);
    if (lane == 0) rbuf[wid] = v;
    __syncthreads();
    if (wid == 0) {
        float r = (lane < 32) ? rbuf[lane] : -3.402823466e38f;
        r = warpMax(r);
        if (lane == 0) rbuf[32] = r;
    }
    __syncthreads();
    float r = rbuf[32];
    __syncthreads();
    return r;
}

// -------- cp conv3 (2 channels) + LN + leaky + softmax + gaussian prep ------
// One block per batch, 1024 threads (one per l).
__global__ __launch_bounds__(1024) void cp3_kernel(
    const float* __restrict__ w3, const float* __restrict__ b3)
{
    __shared__ float w3s[2 * DD2 * 3];   // 30 KB
    __shared__ float rbuf[33];
    int b = blockIdx.x, tid = threadIdx.x;
    for (int i = tid; i < 2 * DD2 * 3; i += 1024) w3s[i] = w3[i];
    __syncthreads();

    const float* xb = g_act2 + (size_t)b * DD2 * LPAD + (OFF - 1) + tid;
    float a0 = b3[0], a1 = b3[1];
    for (int i = 0; i < DD2; ++i) {
        const float* xr = xb + (size_t)i * LPAD;
        float x0 = xr[0], x1 = xr[1], x2 = xr[2];
        const float* wv0 = &w3s[i * 3];
        const float* wv1 = &w3s[3 * DD2 + i * 3];
        a0 += wv0[0] * x0 + wv0[1] * x1 + wv0[2] * x2;
        a1 += wv1[0] * x0 + wv1[1] * x1 + wv1[2] * x2;
    }
    // LayerNorm over the 2*L values of this batch
    float s = blockSum(a0 + a1, rbuf);
    float q = blockSum(a0 * a0 + a1 * a1, rbuf);
    float mean = s * (1.f / (2.f * LL));
    float var  = q * (1.f / (2.f * LL)) - mean * mean;
    float rstd = rsqrtf(var + 1e-5f);
    float v0 = (a0 - mean) * rstd; v0 = v0 >= 0.f ? v0 : 0.01f * v0;
    float v1 = (a1 - mean) * rstd; v1 = v1 >= 0.f ? v1 : 0.01f * v1;
    // softmax channel 0 -> s -> std -> gaussian coefficient a = 1/(1e-5+2 std^2)
    float m0 = blockMax(v0, rbuf);
    float e0 = expf(v0 - m0);
    float s0 = blockSum(e0, rbuf);
    float smx = e0 / s0;
    float std = 0.1f * (float)LL * smx;
    g_arow[b * LL + tid] = 1.f / (1e-5f + 2.f * std * std);
    // softmax channel 1 -> w
    float m1 = blockMax(v1, rbuf);
    float e1 = expf(v1 - m1);
    float s1 = blockSum(e1, rbuf);
    g_wsm[b * LL + tid] = e1 / s1;
}

// ------------------------- build pooling matrix W ---------------------------
// W[b,i,j] = exp(-(i-j)^2 * a_i) * w_j   (prefactor cancels with max-normalize)
__global__ void build_w_kernel() {
    int b = blockIdx.z;
    int i = blockIdx.y;
    int j = blockIdx.x * 256 + threadIdx.x;
    float a = g_arow[b * LL + i];
    float d = (float)(i - j);
    float t = d * d * a;
    float val = 0.f;
    if (t < 88.f) val = __expf(-t) * g_wsm[b * LL + j];
    g_Wmat[((size_t)b * LL + i) * LL + j] = val;
}

// ------------- pooling GEMM: out_sa = W @ feats + feats -> g_cat[:, :D] -----
__global__ __launch_bounds__(256) void pool_gemm_kernel(const float* __restrict__ feats) {
    int b = blockIdx.z, m0 = blockIdx.y * 128, n0 = blockIdx.x * 128, tid = threadIdx.x;
    const float* A  = g_Wmat + (size_t)b * LL * LL;
    const float* Bf = feats  + (size_t)b * LL * DD;
    __shared__ float As[16][128];
    __shared__ float Bs[16][128];
    float acc[8][8];
#pragma unroll
    for (int i = 0; i < 8; ++i)
#pragma unroll
        for (int j = 0; j < 8; ++j) acc[i][j] = 0.f;

    const int mS = (tid >> 4) * 8, nS = (tid & 15) * 8;
    const int ar = tid >> 2, ac = (tid & 3) * 4;
    const int bn4 = (tid & 31) * 4, bkr = tid >> 5;

    for (int k0 = 0; k0 < LL; k0 += 16) {
#pragma unroll
        for (int h = 0; h < 2; ++h) {
            int row = ar + h * 64;
            float4 v = *(const float4*)(A + (size_t)(m0 + row) * LL + k0 + ac);
            As[ac + 0][row] = v.x; As[ac + 1][row] = v.y;
            As[ac + 2][row] = v.z; As[ac + 3][row] = v.w;
        }
#pragma unroll
        for (int h = 0; h < 2; ++h) {
            int k = bkr + h * 8;
            float4 v = *(const float4*)(Bf + (size_t)(k0 + k) * DD + n0 + bn4);
            *(float4*)&Bs[k][bn4] = v;
        }
        __syncthreads();
#pragma unroll
        for (int kk = 0; kk < 16; ++kk) {
            float rm[8], rn[8];
            *(float4*)&rm[0] = *(const float4*)&As[kk][mS];
            *(float4*)&rm[4] = *(const float4*)&As[kk][mS + 4];
            *(float4*)&rn[0] = *(const float4*)&Bs[kk][nS];
            *(float4*)&rn[4] = *(const float4*)&Bs[kk][nS + 4];
#pragma unroll
            for (int i = 0; i < 8; ++i)
#pragma unroll
                for (int j = 0; j < 8; ++j)
                    acc[i][j] = fmaf(rm[i], rn[j], acc[i][j]);
        }
        __syncthreads();
    }
#pragma unroll
    for (int i = 0; i < 8; ++i) {
        int m = m0 + mS + i;
        const float* fr = feats + ((size_t)b * LL + m) * DD + n0 + nS;
        float* cr = g_cat + ((size_t)b * LL + m) * (2 * DD) + n0 + nS;
        float4 f0 = *(const float4*)fr, f1 = *(const float4*)(fr + 4);
        *(float4*)cr       = make_float4(acc[i][0] + f0.x, acc[i][1] + f0.y,
                                         acc[i][2] + f0.z, acc[i][3] + f0.w);
        *(float4*)(cr + 4) = make_float4(acc[i][4] + f1.x, acc[i][5] + f1.y,
                                         acc[i][6] + f1.z, acc[i][7] + f1.w);
    }
}

// -------- transpose cv3 [B,D,L] -> + feats -> g_cat[:, D:2D] ----------------
__global__ void transpose_add_kernel(const float* __restrict__ feats) {
    __shared__ float t[32][33];
    int b = blockIdx.z;
    int l0 = blockIdx.x * 32, d0 = blockIdx.y * 32;
    int tx = threadIdx.x, ty = threadIdx.y;
#pragma unroll
    for (int y = 0; y < 32; y += 8)
        t[ty + y][tx] = g_cv3[((size_t)b * DD + d0 + ty + y) * LPAD + OFF + l0 + tx]; // t[d][l]
    __syncthreads();
#pragma unroll
    for (int y = 0; y < 32; y += 8) {
        int l = l0 + ty + y, d = d0 + tx;
        g_cat[((size_t)b * LL + l) * (2 * DD) + DD + d] =
            t[tx][ty + y] + feats[((size_t)b * LL + l) * DD + d];
    }
}

// ------------------------------- MLP GEMM -----------------------------------
// out[m, n] = leaky( sum_k cat[m,k] * Wm[n,k] + bias[n] ),  m = b*L + l
__global__ __launch_bounds__(256) void mlp_gemm_kernel(
    const float* __restrict__ Wm, const float* __restrict__ bias,
    float* __restrict__ out)
{
    int m0 = blockIdx.y * 128, n0 = blockIdx.x * 128, tid = threadIdx.x;
    const int K = 2 * DD;
    __shared__ float As[16][128];
    __shared__ float Bs[16][128];
    float acc[8][8];
#pragma unroll
    for (int i = 0; i < 8; ++i)
#pragma unroll
        for (int j = 0; j < 8; ++j) acc[i][j] = 0.f;

    const int mS = (tid >> 4) * 8, nS = (tid & 15) * 8;
    const int ar = tid >> 2, ac = (tid & 3) * 4;

    for (int k0 = 0; k0 < K; k0 += 16) {
#pragma unroll
        for (int h = 0; h < 2; ++h) {
            int row = ar + h * 64;
            float4 v = *(const float4*)(g_cat + (size_t)(m0 + row) * K + k0 + ac);
            As[ac + 0][row] = v.x; As[ac + 1][row] = v.y;
            As[ac + 2][row] = v.z; As[ac + 3][row] = v.w;
        }
#pragma unroll
        for (int h = 0; h < 2; ++h) {
            int row = ar + h * 64;
            float4 v = *(const float4*)(Wm + (size_t)(n0 + row) * K + k0 + ac);
            Bs[ac + 0][row] = v.x; Bs[ac + 1][row] = v.y;
            Bs[ac + 2][row] = v.z; Bs[ac + 3][row] = v.w;
        }
        __syncthreads();
#pragma unroll
        for (int kk = 0; kk < 16; ++kk) {
            float rm[8], rn[8];
            *(float4*)&rm[0] = *(const float4*)&As[kk][mS];
            *(float4*)&rm[4] = *(const float4*)&As[kk][mS + 4];
            *(float4*)&rn[0] = *(const float4*)&Bs[kk][nS];
            *(float4*)&rn[4] = *(const float4*)&Bs[kk][nS + 4];
#pragma unroll
            for (int i = 0; i < 8; ++i)
#pragma unroll
                for (int j = 0; j < 8; ++j)
                    acc[i][j] = fmaf(rm[i], rn[j], acc[i][j]);
        }
        __syncthreads();
    }
#pragma unroll
    for (int i = 0; i < 8; ++i) {
        int m = m0 + mS + i;
#pragma unroll
        for (int j = 0; j < 8; ++j) {
            int n = n0 + nS + j;
            float v = acc[i][j] + bias[n];
            v = v >= 0.f ? v : 0.01f * v;
            out[(size_t)m * DD + n] = v;
        }
    }
}

// ------------------------------ launch --------------------------------------
extern "C" void kernel_launch(void* const* d_in, const int* in_sizes, int n_in,
                              void* d_out, int out_size)
{
    (void)in_sizes; (void)n_in; (void)out_size;
    const float* feats = (const float*)d_in[0];
    const float* cp_w1 = (const float*)d_in[1];
    const float* cp_b1 = (const float*)d_in[2];
    const float* cp_w2 = (const float*)d_in[3];
    const float* cp_b2 = (const float*)d_in[4];
    const float* cp_w3 = (const float*)d_in[5];
    const float* cp_b3 = (const float*)d_in[6];
    const float* cv_w1 = (const float*)d_in[7];
    const float* cv_b1 = (const float*)d_in[8];
    const float* cv_w2 = (const float*)d_in[9];
    const float* cv_b2 = (const float*)d_in[10];
    const float* cv_w3 = (const float*)d_in[11];
    const float* cv_b3 = (const float*)d_in[12];
    const float* mlp_w = (const float*)d_in[13];
    const float* mlp_b = (const float*)d_in[14];
    float* out = (float*)d_out;

    float *featsT, *act1, *act2, *cv3;
    cudaGetSymbolAddress((void**)&featsT, g_featsT);
    cudaGetSymbolAddress((void**)&act1,   g_act1);
    cudaGetSymbolAddress((void**)&act2,   g_act2);
    cudaGetSymbolAddress((void**)&cv3,    g_cv3);

    const int nPadRows = BN * (DD + DD2 + DD2 + DD);
    init_pads_kernel<<<(nPadRows + 255) / 256, 256>>>();
    transpose_feats_kernel<<<dim3(DD / 32, LL / 32, BN), dim3(32, 8)>>>(feats);

    // ---- ContextPooling conv stack ----
    conv_gemm_kernel<<<dim3(8, DD2 / 128, BN), 256>>>(cp_w1, cp_b1, featsT, act1, DD2, DD);
    ln_leaky_kernel<<<dim3(64, BN), 256>>>(act1, DD2, 80);
    conv_gemm_kernel<<<dim3(8, DD2 / 128, BN), 256>>>(cp_w2, cp_b2, act1, act2, DD2, DD2);
    ln_leaky_kernel<<<dim3(64, BN), 256>>>(act2, DD2, 80);
    cp3_kernel<<<BN, 1024>>>(cp_w3, cp_b3);
    build_w_kernel<<<dim3(LL / 256, LL, BN), 256>>>();
    pool_gemm_kernel<<<dim3(DD / 128, LL / 128, BN), 256>>>(feats);

    // ---- SoluModel conv stack ----
    conv_gemm_kernel<<<dim3(8, DD2 / 128, BN), 256>>>(cv_w1, cv_b1, featsT, act1, DD2, DD);
    ln_leaky_kernel<<<dim3(64, BN), 256>>>(act1, DD2, 80);
    conv_gemm_kernel<<<dim3(8, DD2 / 128, BN), 256>>>(cv_w2, cv_b2, act1, act2, DD2, DD2);
    ln_leaky_kernel<<<dim3(64, BN), 256>>>(act2, DD2, 80);
    conv_gemm_kernel<<<dim3(8, DD / 128, BN), 256>>>(cv_w3, cv_b3, act2, cv3, DD, DD2);
    ln_leaky_kernel<<<dim3(64, BN), 256>>>(cv3, DD, 40);
    transpose_add_kernel<<<dim3(LL / 32, DD / 32, BN), dim3(32, 8)>>>(feats);

    // ---- MLP ----
    mlp_gemm_kernel<<<dim3(DD / 128, (BN * LL) / 128), 256>>>(mlp_w, mlp_b, out);
}

// round 3
// speedup vs baseline: 1.0013x; 1.0013x over previous
#include <cuda_runtime.h>

// ---------------------------------------------------------------------------
// SoluModel fused pipeline, fp32 baseline.
// B=16, L=1024, D=640, D2=1280. All activations [B, C, LPAD] with interior
// at column OFF..OFF+L-1; columns OFF-1 and OFF+L are zero (conv SAME pad).
// ---------------------------------------------------------------------------

#define BN   16
#define LL   1024
#define DD   640
#define DD2  1280
#define LPAD 1032   // padded row length (keeps float4 alignment with OFF=4)
#define OFF  4

// ------------------------- device scratch buffers --------------------------
__device__ float g_featsT[(size_t)BN * DD  * LPAD];  // feats transposed [B,D,LPAD]
__device__ float g_act1  [(size_t)BN * DD2 * LPAD];  // conv stage buffer
__device__ float g_act2  [(size_t)BN * DD2 * LPAD];  // conv stage buffer
__device__ float g_cv3   [(size_t)BN * DD  * LPAD];  // cv conv3 out
__device__ float g_Wmat  [(size_t)BN * LL  * LL];    // pooling weight matrix
__device__ float g_cat   [(size_t)BN * LL  * (2*DD)];// [out_sa | out_conv]
__device__ float g_arow  [BN * LL];                  // 1/(1e-5 + 2*std^2)
__device__ float g_wsm   [BN * LL];                  // softmax(w channel)
__device__ float2 g_part [BN * 80];                  // LN partial (sum, sumsq)

// ------------------------------ init pads ----------------------------------
__global__ void init_pads_kernel() {
    int idx = blockIdx.x * blockDim.x + threadIdx.x;
    const int nfT = BN * DD, na = BN * DD2;
    float* base; int r;
    if      (idx < nfT)            { base = g_featsT; r = idx; }
    else if (idx < nfT + na)       { base = g_act1;   r = idx - nfT; }
    else if (idx < nfT + 2*na)     { base = g_act2;   r = idx - nfT - na; }
    else if (idx < nfT + 2*na + BN*DD) { base = g_cv3; r = idx - nfT - 2*na; }
    else return;
    base[(size_t)r * LPAD + (OFF - 1)]  = 0.f;
    base[(size_t)r * LPAD + (OFF + LL)] = 0.f;
}

// --------------------------- transpose feats -------------------------------
// feats [B,L,D] -> g_featsT [B,D,LPAD] interior
__global__ void transpose_feats_kernel(const float* __restrict__ feats) {
    __shared__ float t[32][33];
    int b = blockIdx.z;
    int d0 = blockIdx.x * 32, l0 = blockIdx.y * 32;
    int tx = threadIdx.x, ty = threadIdx.y;
#pragma unroll
    for (int y = 0; y < 32; y += 8)
        t[ty + y][tx] = feats[((size_t)b * LL + l0 + ty + y) * DD + d0 + tx]; // t[l][d]
    __syncthreads();
#pragma unroll
    for (int y = 0; y < 32; y += 8)
        g_featsT[((size_t)b * DD + d0 + ty + y) * LPAD + OFF + l0 + tx] = t[tx][ty + y];
}

// ------------------------------ conv GEMM ----------------------------------
// y[b,o,l] = sum_{i,t} w[o,i,t] * xpad[b,i,l+t-1] + bias[o]
// As NT GEMM: A = w [M, K=3*IC] (K-contiguous), B[n=l, k] = xpad[b, k/3, l + k%3]
// Writes per-block LN partials (deterministic, no atomics).
__global__ __launch_bounds__(256) void conv_gemm_kernel(
    const float* __restrict__ Aw, const float* __restrict__ bias,
    const float* __restrict__ Xpad, float* __restrict__ Ypad,
    int M, int IC)
{
    const int K  = 3 * IC;
    const int b  = blockIdx.z;
    const int m0 = blockIdx.y * 128, n0 = blockIdx.x * 128;
    const int tid = threadIdx.x;
    __shared__ float As[16][128];
    __shared__ float Bs[16][128];
    float acc[8][8];
#pragma unroll
    for (int i = 0; i < 8; ++i)
#pragma unroll
        for (int j = 0; j < 8; ++j) acc[i][j] = 0.f;

    const int mS = (tid >> 4) * 8, nS = (tid & 15) * 8;
    const int ar = tid >> 2, ac = (tid & 3) * 4;
    const int bn = tid & 127, bk = tid >> 7;
    const float* Xb = Xpad + (size_t)b * IC * LPAD + n0 + (OFF - 1);

    for (int k0 = 0; k0 < K; k0 += 16) {
#pragma unroll
        for (int h = 0; h < 2; ++h) {
            int row = ar + h * 64;
            float4 v = *(const float4*)(Aw + (size_t)(m0 + row) * K + k0 + ac);
            As[ac + 0][row] = v.x; As[ac + 1][row] = v.y;
            As[ac + 2][row] = v.z; As[ac + 3][row] = v.w;
        }
#pragma unroll
        for (int h = 0; h < 8; ++h) {
            int k  = bk + h * 2;
            int kk = k0 + k;
            int ic = kk / 3;
            int t  = kk - ic * 3;
            Bs[k][bn] = Xb[(size_t)ic * LPAD + bn + t];
        }
        __syncthreads();
#pragma unroll
        for (int kk = 0; kk < 16; ++kk) {
            float rm[8], rn[8];
            *(float4*)&rm[0] = *(const float4*)&As[kk][mS];
            *(float4*)&rm[4] = *(const float4*)&As[kk][mS + 4];
            *(float4*)&rn[0] = *(const float4*)&Bs[kk][nS];
            *(float4*)&rn[4] = *(const float4*)&Bs[kk][nS + 4];
#pragma unroll
            for (int i = 0; i < 8; ++i)
#pragma unroll
                for (int j = 0; j < 8; ++j)
                    acc[i][j] = fmaf(rm[i], rn[j], acc[i][j]);
        }
        __syncthreads();
    }

    float s = 0.f, q = 0.f;
#pragma unroll
    for (int i = 0; i < 8; ++i) {
        int m = m0 + mS + i;
        float bv = bias[m];
        float* yr = Ypad + ((size_t)b * M + m) * LPAD + OFF + n0 + nS;
        float v0[8];
#pragma unroll
        for (int j = 0; j < 8; ++j) { float v = acc[i][j] + bv; v0[j] = v; s += v; q += v * v; }
        *(float4*)yr       = make_float4(v0[0], v0[1], v0[2], v0[3]);
        *(float4*)(yr + 4) = make_float4(v0[4], v0[5], v0[6], v0[7]);
    }
#pragma unroll
    for (int o = 16; o > 0; o >>= 1) {
        s += __shfl_xor_sync(0xffffffffu, s, o);
        q += __shfl_xor_sync(0xffffffffu, q, o);
    }
    __shared__ float2 rb[8];
    if ((tid & 31) == 0) rb[tid >> 5] = make_float2(s, q);
    __syncthreads();
    if (tid == 0) {
        float S = 0.f, Q = 0.f;
#pragma unroll
        for (int i = 0; i < 8; ++i) { S += rb[i].x; Q += rb[i].y; }
        g_part[(size_t)b * 80 + blockIdx.y * gridDim.x + blockIdx.x] = make_float2(S, Q);
    }
}

// --------------------------- LayerNorm + Leaky ------------------------------
__global__ __launch_bounds__(256) void ln_leaky_kernel(
    float* __restrict__ X, int C, int nPart)
{
    int b = blockIdx.y, tid = threadIdx.x;
    float s = 0.f, q = 0.f;
    if (tid < nPart) { float2 p = g_part[(size_t)b * 80 + tid]; s = p.x; q = p.y; }
#pragma unroll
    for (int o = 16; o > 0; o >>= 1) {
        s += __shfl_xor_sync(0xffffffffu, s, o);
        q += __shfl_xor_sync(0xffffffffu, q, o);
    }
    __shared__ float2 rb[8];
    __shared__ float sm[2];
    if ((tid & 31) == 0) rb[tid >> 5] = make_float2(s, q);
    __syncthreads();
    if (tid == 0) {
        float S = 0.f, Q = 0.f;
        for (int i = 0; i < 8; ++i) { S += rb[i].x; Q += rb[i].y; }
        float inv  = 1.f / ((float)C * (float)LL);
        float mean = S * inv;
        float var  = Q * inv - mean * mean;
        sm[0] = mean; sm[1] = rsqrtf(var + 1e-5f);
    }
    __syncthreads();
    float mean = sm[0], rstd = sm[1];
    size_t total = (size_t)C * LL;
    for (size_t idx = (size_t)blockIdx.x * 256 + tid; idx < total; idx += (size_t)gridDim.x * 256) {
        size_t c = idx >> 10;
        int l = (int)(idx & 1023);
        float* p = X + ((size_t)b * C + c) * LPAD + OFF + l;
        float v = (*p - mean) * rstd;
        *p = v >= 0.f ? v : 0.01f * v;
    }
}

// ------------------------ reductions (1024-thread block) --------------------
__device__ __forceinline__ float warpSum(float v) {
#pragma unroll
    for (int o = 16; o > 0; o >>= 1) v += __shfl_xor_sync(0xffffffffu, v, o);
    return v;
}
__device__ __forceinline__ float warpMax(float v) {
#pragma unroll
    for (int o = 16; o > 0; o >>= 1) v = fmaxf(v, __shfl_xor_sync(0xffffffffu, v, o));
    return v;
}
__device__ float blockSum(float v, float* rbuf) {
    int lane = threadIdx.x & 31, wid = threadIdx.x >> 5;
    v = warpSum(v);
    if (lane == 0) rbuf[wid] = v;
    __syncthreads();
    if (wid == 0) {
        float r = (lane < 32) ? rbuf[lane] : 0.f;
        r = warpSum(r);
        if (lane == 0) rbuf[32] = r;
    }
    __syncthreads();
    float r = rbuf[32];
    __syncthreads();
    return r;
}
__device__ float blockMax(float v, float* rbuf) {
    int lane = threadIdx.x & 31, wid = threadIdx.x >> 5;
    v = warpMax(v);
    if (lane == 0) rbuf[wid] = v;
    __syncthreads();
    if (wid == 0) {
        float r = (lane < 32) ? rbuf[lane] : -3.402823466e38f;
        r = warpMax(r);
        if (lane == 0) rbuf[32] = r;
    }
    __syncthreads();
    float r = rbuf[32];
    __syncthreads();
    return r;
}

// -------- cp conv3 (2 channels) + LN + leaky + softmax + gaussian prep ------
// One block per batch, 1024 threads (one per l).
__global__ __launch_bounds__(1024) void cp3_kernel(
    const float* __restrict__ w3, const float* __restrict__ b3)
{
    __shared__ float w3s[2 * DD2 * 3];   // 30 KB
    __shared__ float rbuf[33];
    int b = blockIdx.x, tid = threadIdx.x;
    for (int i = tid; i < 2 * DD2 * 3; i += 1024) w3s[i] = w3[i];
    __syncthreads();

    const float* xb = g_act2 + (size_t)b * DD2 * LPAD + (OFF - 1) + tid;
    float a0 = b3[0], a1 = b3[1];
    for (int i = 0; i < DD2; ++i) {
        const float* xr = xb + (size_t)i * LPAD;
        float x0 = xr[0], x1 = xr[1], x2 = xr[2];
        const float* wv0 = &w3s[i * 3];
        const float* wv1 = &w3s[3 * DD2 + i * 3];
        a0 += wv0[0] * x0 + wv0[1] * x1 + wv0[2] * x2;
        a1 += wv1[0] * x0 + wv1[1] * x1 + wv1[2] * x2;
    }
    // LayerNorm over the 2*L values of this batch
    float s = blockSum(a0 + a1, rbuf);
    float q = blockSum(a0 * a0 + a1 * a1, rbuf);
    float mean = s * (1.f / (2.f * LL));
    float var  = q * (1.f / (2.f * LL)) - mean * mean;
    float rstd = rsqrtf(var + 1e-5f);
    float v0 = (a0 - mean) * rstd; v0 = v0 >= 0.f ? v0 : 0.01f * v0;
    float v1 = (a1 - mean) * rstd; v1 = v1 >= 0.f ? v1 : 0.01f * v1;
    // softmax channel 0 -> s -> std -> gaussian coefficient a = 1/(1e-5+2 std^2)
    float m0 = blockMax(v0, rbuf);
    float e0 = expf(v0 - m0);
    float s0 = blockSum(e0, rbuf);
    float smx = e0 / s0;
    float std = 0.1f * (float)LL * smx;
    g_arow[b * LL + tid] = 1.f / (1e-5f + 2.f * std * std);
    // softmax channel 1 -> w
    float m1 = blockMax(v1, rbuf);
    float e1 = expf(v1 - m1);
    float s1 = blockSum(e1, rbuf);
    g_wsm[b * LL + tid] = e1 / s1;
}

// ------------------------- build pooling matrix W ---------------------------
// W[b,i,j] = exp(-(i-j)^2 * a_i) * w_j   (prefactor cancels with max-normalize)
__global__ void build_w_kernel() {
    int b = blockIdx.z;
    int i = blockIdx.y;
    int j = blockIdx.x * 256 + threadIdx.x;
    float a = g_arow[b * LL + i];
    float d = (float)(i - j);
    float t = d * d * a;
    float val = 0.f;
    if (t < 88.f) val = __expf(-t) * g_wsm[b * LL + j];
    g_Wmat[((size_t)b * LL + i) * LL + j] = val;
}

// ------------- pooling GEMM: out_sa = W @ feats + feats -> g_cat[:, :D] -----
__global__ __launch_bounds__(256) void pool_gemm_kernel(const float* __restrict__ feats) {
    int b = blockIdx.z, m0 = blockIdx.y * 128, n0 = blockIdx.x * 128, tid = threadIdx.x;
    const float* A  = g_Wmat + (size_t)b * LL * LL;
    const float* Bf = feats  + (size_t)b * LL * DD;
    __shared__ float As[16][128];
    __shared__ float Bs[16][128];
    float acc[8][8];
#pragma unroll
    for (int i = 0; i < 8; ++i)
#pragma unroll
        for (int j = 0; j < 8; ++j) acc[i][j] = 0.f;

    const int mS = (tid >> 4) * 8, nS = (tid & 15) * 8;
    const int ar = tid >> 2, ac = (tid & 3) * 4;
    const int bn4 = (tid & 31) * 4, bkr = tid >> 5;

    for (int k0 = 0; k0 < LL; k0 += 16) {
#pragma unroll
        for (int h = 0; h < 2; ++h) {
            int row = ar + h * 64;
            float4 v = *(const float4*)(A + (size_t)(m0 + row) * LL + k0 + ac);
            As[ac + 0][row] = v.x; As[ac + 1][row] = v.y;
            As[ac + 2][row] = v.z; As[ac + 3][row] = v.w;
        }
#pragma unroll
        for (int h = 0; h < 2; ++h) {
            int k = bkr + h * 8;
            float4 v = *(const float4*)(Bf + (size_t)(k0 + k) * DD + n0 + bn4);
            *(float4*)&Bs[k][bn4] = v;
        }
        __syncthreads();
#pragma unroll
        for (int kk = 0; kk < 16; ++kk) {
            float rm[8], rn[8];
            *(float4*)&rm[0] = *(const float4*)&As[kk][mS];
            *(float4*)&rm[4] = *(const float4*)&As[kk][mS + 4];
            *(float4*)&rn[0] = *(const float4*)&Bs[kk][nS];
            *(float4*)&rn[4] = *(const float4*)&Bs[kk][nS + 4];
#pragma unroll
            for (int i = 0; i < 8; ++i)
#pragma unroll
                for (int j = 0; j < 8; ++j)
                    acc[i][j] = fmaf(rm[i], rn[j], acc[i][j]);
        }
        __syncthreads();
    }
#pragma unroll
    for (int i = 0; i < 8; ++i) {
        int m = m0 + mS + i;
        const float* fr = feats + ((size_t)b * LL + m) * DD + n0 + nS;
        float* cr = g_cat + ((size_t)b * LL + m) * (2 * DD) + n0 + nS;
        float4 f0 = *(const float4*)fr, f1 = *(const float4*)(fr + 4);
        *(float4*)cr       = make_float4(acc[i][0] + f0.x, acc[i][1] + f0.y,
                                         acc[i][2] + f0.z, acc[i][3] + f0.w);
        *(float4*)(cr + 4) = make_float4(acc[i][4] + f1.x, acc[i][5] + f1.y,
                                         acc[i][6] + f1.z, acc[i][7] + f1.w);
    }
}

// -------- transpose cv3 [B,D,L] -> + feats -> g_cat[:, D:2D] ----------------
__global__ void transpose_add_kernel(const float* __restrict__ feats) {
    __shared__ float t[32][33];
    int b = blockIdx.z;
    int l0 = blockIdx.x * 32, d0 = blockIdx.y * 32;
    int tx = threadIdx.x, ty = threadIdx.y;
#pragma unroll
    for (int y = 0; y < 32; y += 8)
        t[ty + y][tx] = g_cv3[((size_t)b * DD + d0 + ty + y) * LPAD + OFF + l0 + tx]; // t[d][l]
    __syncthreads();
#pragma unroll
    for (int y = 0; y < 32; y += 8) {
        int l = l0 + ty + y, d = d0 + tx;
        g_cat[((size_t)b * LL + l) * (2 * DD) + DD + d] =
            t[tx][ty + y] + feats[((size_t)b * LL + l) * DD + d];
    }
}

// ------------------------------- MLP GEMM -----------------------------------
// out[m, n] = leaky( sum_k cat[m,k] * Wm[n,k] + bias[n] ),  m = b*L + l
__global__ __launch_bounds__(256) void mlp_gemm_kernel(
    const float* __restrict__ Wm, const float* __restrict__ bias,
    float* __restrict__ out)
{
    int m0 = blockIdx.y * 128, n0 = blockIdx.x * 128, tid = threadIdx.x;
    const int K = 2 * DD;
    __shared__ float As[16][128];
    __shared__ float Bs[16][128];
    float acc[8][8];
#pragma unroll
    for (int i = 0; i < 8; ++i)
#pragma unroll
        for (int j = 0; j < 8; ++j) acc[i][j] = 0.f;

    const int mS = (tid >> 4) * 8, nS = (tid & 15) * 8;
    const int ar = tid >> 2, ac = (tid & 3) * 4;

    for (int k0 = 0; k0 < K; k0 += 16) {
#pragma unroll
        for (int h = 0; h < 2; ++h) {
            int row = ar + h * 64;
            float4 v = *(const float4*)(g_cat + (size_t)(m0 + row) * K + k0 + ac);
            As[ac + 0][row] = v.x; As[ac + 1][row] = v.y;
            As[ac + 2][row] = v.z; As[ac + 3][row] = v.w;
        }
#pragma unroll
        for (int h = 0; h < 2; ++h) {
            int row = ar + h * 64;
            float4 v = *(const float4*)(Wm + (size_t)(n0 + row) * K + k0 + ac);
            Bs[ac + 0][row] = v.x; Bs[ac + 1][row] = v.y;
            Bs[ac + 2][row] = v.z; Bs[ac + 3][row] = v.w;
        }
        __syncthreads();
#pragma unroll
        for (int kk = 0; kk < 16; ++kk) {
            float rm[8], rn[8];
            *(float4*)&rm[0] = *(const float4*)&As[kk][mS];
            *(float4*)&rm[4] = *(const float4*)&As[kk][mS + 4];
            *(float4*)&rn[0] = *(const float4*)&Bs[kk][nS];
            *(float4*)&rn[4] = *(const float4*)&Bs[kk][nS + 4];
#pragma unroll
            for (int i = 0; i < 8; ++i)
#pragma unroll
                for (int j = 0; j < 8; ++j)
                    acc[i][j] = fmaf(rm[i], rn[j], acc[i][j]);
        }
        __syncthreads();
    }
#pragma unroll
    for (int i = 0; i < 8; ++i) {
        int m = m0 + mS + i;
#pragma unroll
        for (int j = 0; j < 8; ++j) {
            int n = n0 + nS + j;
            float v = acc[i][j] + bias[n];
            v = v >= 0.f ? v : 0.01f * v;
            out[(size_t)m * DD + n] = v;
        }
    }
}

// ------------------------------ launch --------------------------------------
extern "C" void kernel_launch(void* const* d_in, const int* in_sizes, int n_in,
                              void* d_out, int out_size)
{
    (void)in_sizes; (void)n_in; (void)out_size;
    const float* feats = (const float*)d_in[0];
    const float* cp_w1 = (const float*)d_in[1];
    const float* cp_b1 = (const float*)d_in[2];
    const float* cp_w2 = (const float*)d_in[3];
    const float* cp_b2 = (const float*)d_in[4];
    const float* cp_w3 = (const float*)d_in[5];
    const float* cp_b3 = (const float*)d_in[6];
    const float* cv_w1 = (const float*)d_in[7];
    const float* cv_b1 = (const float*)d_in[8];
    const float* cv_w2 = (const float*)d_in[9];
    const float* cv_b2 = (const float*)d_in[10];
    const float* cv_w3 = (const float*)d_in[11];
    const float* cv_b3 = (const float*)d_in[12];
    const float* mlp_w = (const float*)d_in[13];
    const float* mlp_b = (const float*)d_in[14];
    float* out = (float*)d_out;

    float *featsT, *act1, *act2, *cv3;
    cudaGetSymbolAddress((void**)&featsT, g_featsT);
    cudaGetSymbolAddress((void**)&act1,   g_act1);
    cudaGetSymbolAddress((void**)&act2,   g_act2);
    cudaGetSymbolAddress((void**)&cv3,    g_cv3);

    const int nPadRows = BN * (DD + DD2 + DD2 + DD);
    init_pads_kernel<<<(nPadRows + 255) / 256, 256>>>();
    transpose_feats_kernel<<<dim3(DD / 32, LL / 32, BN), dim3(32, 8)>>>(feats);

    // ---- ContextPooling conv stack ----
    conv_gemm_kernel<<<dim3(8, DD2 / 128, BN), 256>>>(cp_w1, cp_b1, featsT, act1, DD2, DD);
    ln_leaky_kernel<<<dim3(64, BN), 256>>>(act1, DD2, 80);
    conv_gemm_kernel<<<dim3(8, DD2 / 128, BN), 256>>>(cp_w2, cp_b2, act1, act2, DD2, DD2);
    ln_leaky_kernel<<<dim3(64, BN), 256>>>(act2, DD2, 80);
    cp3_kernel<<<BN, 1024>>>(cp_w3, cp_b3);
    build_w_kernel<<<dim3(LL / 256, LL, BN), 256>>>();
    pool_gemm_kernel<<<dim3(DD / 128, LL / 128, BN), 256>>>(feats);

    // ---- SoluModel conv stack ----
    conv_gemm_kernel<<<dim3(8, DD2 / 128, BN), 256>>>(cv_w1, cv_b1, featsT, act1, DD2, DD);
    ln_leaky_kernel<<<dim3(64, BN), 256>>>(act1, DD2, 80);
    conv_gemm_kernel<<<dim3(8, DD2 / 128, BN), 256>>>(cv_w2, cv_b2, act1, act2, DD2, DD2);
    ln_leaky_kernel<<<dim3(64, BN), 256>>>(act2, DD2, 80);
    conv_gemm_kernel<<<dim3(8, DD / 128, BN), 256>>>(cv_w3, cv_b3, act2, cv3, DD, DD2);
    ln_leaky_kernel<<<dim3(64, BN), 256>>>(cv3, DD, 40);
    transpose_add_kernel<<<dim3(LL / 32, DD / 32, BN), dim3(32, 8)>>>(feats);

    // ---- MLP ----
    mlp_gemm_kernel<<<dim3(DD / 128, (BN * LL) / 128), 256>>>(mlp_w, mlp_b, out);
}